// round 3
// baseline (speedup 1.0000x reference)
#include <cuda_runtime.h>

#define BDIM 2
#define LDIM 4096
#define HDIM 8
#define DDIM 64
#define MDIM 128
#define CHK  128
#define NCH  (LDIM / CHK)     // 32
#define NBH  (BDIM * HDIM)    // 16

#define TSTRIDE 132           // padded stride for d-major transposed tiles (16B-aligned rows)
#define KPTSTRIDE 129         // padded stride for kpT (conflict-free transpose stores)
#define RATIO 0.08838834764831845f   // 1/sqrt(128)
#define STAB  1e-3f

typedef unsigned long long u64;

// ---- packed f32x2 helpers (Blackwell FFMA2 path) ----
__device__ __forceinline__ u64 pk2(float a, float b) {
    u64 r;
    asm("mov.b64 %0, {%1, %2};" : "=l"(r) : "r"(__float_as_uint(a)), "r"(__float_as_uint(b)));
    return r;
}
__device__ __forceinline__ u64 pk1(float a) { return pk2(a, a); }
__device__ __forceinline__ void fma2(u64& d, u64 a, u64 b) {
    asm("fma.rn.f32x2 %0, %1, %2, %0;" : "+l"(d) : "l"(a), "l"(b));
}
__device__ __forceinline__ void upk(u64 v, float& a, float& b) {
    unsigned x, y;
    asm("mov.b64 {%0, %1}, %2;" : "=r"(x), "=r"(y) : "l"(v));
    a = __uint_as_float(x); b = __uint_as_float(y);
}

// Scratch (device globals; runtime allocation is forbidden)
__device__ float g_kp[(size_t)NBH * LDIM * MDIM];         // [bh][l][m]
__device__ float g_S [(size_t)NBH * NCH * MDIM * DDIM];   // [bh][c][m][d]
__device__ float g_ks[(size_t)NBH * NCH * MDIM];          // [bh][c][m]

// ---------------------------------------------------------------------------
// Pass 1: per-chunk  kp = relu(K P^T * ratio)+eps ;  S_c = kp^T V ; ksum_c
// grid (NCH, NBH), 512 threads
// ---------------------------------------------------------------------------
__global__ __launch_bounds__(512, 1) void pass1_kernel(
    const float* __restrict__ K, const float* __restrict__ V,
    const float* __restrict__ P)
{
    extern __shared__ float sm[];
    float* PsT = sm;                         // 64*132
    float* KsT = PsT + 64 * TSTRIDE;         // 64*132
    float* kps = KsT + 64 * TSTRIDE;         // 128*128
    float* Vs  = kps + CHK * MDIM;           // 128*64

    const int chunk = blockIdx.x;
    const int bh    = blockIdx.y;
    const int b     = bh >> 3;
    const int h     = bh & 7;
    const int l0    = chunk * CHK;
    const int tid   = threadIdx.x;
    const int lane  = tid & 31;
    const int warp  = tid >> 5;

    for (int idx = tid; idx < MDIM * DDIM; idx += 512) {
        int m = idx >> 6, d = idx & 63;
        PsT[d * TSTRIDE + m] = P[idx];
    }
    for (int idx = tid; idx < CHK * DDIM; idx += 512) {
        int c = idx >> 6, d = idx & 63;
        size_t g = ((size_t)((b * LDIM + l0 + c) * HDIM + h)) * DDIM + d;
        KsT[d * TSTRIDE + c] = K[g];
        Vs[c * DDIM + d]     = V[g];
    }
    __syncthreads();

    // kp[c][m] : 4c x 4m tiles. lanes span m (float4 -> 2x f32x2); c broadcast.
    #pragma unroll
    for (int k = 0; k < 2; ++k) {
        const int m0 = (lane) << 2;
        const int c0 = (warp + k * 16) << 2;
        u64 acc[4][2] = {};
        #pragma unroll 8
        for (int d = 0; d < 64; ++d) {
            float4 c4 = *(const float4*)(KsT + d * TSTRIDE + c0);
            ulonglong2 p2 = *(const ulonglong2*)(PsT + d * TSTRIDE + m0);
            u64 cp0 = pk1(c4.x), cp1 = pk1(c4.y), cp2 = pk1(c4.z), cp3 = pk1(c4.w);
            fma2(acc[0][0], cp0, p2.x); fma2(acc[0][1], cp0, p2.y);
            fma2(acc[1][0], cp1, p2.x); fma2(acc[1][1], cp1, p2.y);
            fma2(acc[2][0], cp2, p2.x); fma2(acc[2][1], cp2, p2.y);
            fma2(acc[3][0], cp3, p2.x); fma2(acc[3][1], cp3, p2.y);
        }
        #pragma unroll
        for (int i = 0; i < 4; ++i) {
            float x0, x1, x2, x3;
            upk(acc[i][0], x0, x1); upk(acc[i][1], x2, x3);
            float4 o;
            o.x = fmaxf(x0 * RATIO, 0.f) + STAB;
            o.y = fmaxf(x1 * RATIO, 0.f) + STAB;
            o.z = fmaxf(x2 * RATIO, 0.f) + STAB;
            o.w = fmaxf(x3 * RATIO, 0.f) + STAB;
            *(float4*)(kps + (c0 + i) * MDIM + m0) = o;
        }
    }
    __syncthreads();

    // S_c[m][d] = sum_c kp[c][m] * V[c][d]   (4m x 4d tiles; ksum folded into warp 0)
    float* Sout = g_S + ((size_t)(bh * NCH + chunk)) * MDIM * DDIM;
    {
        const int m0 = lane << 2;
        const int d0 = warp << 2;
        u64 acc[4][2] = {};
        float ks0 = 0.f, ks1 = 0.f, ks2 = 0.f, ks3 = 0.f;
        #pragma unroll 8
        for (int c = 0; c < CHK; ++c) {
            float4 k4 = *(const float4*)(kps + c * MDIM + m0);
            ulonglong2 v2 = *(const ulonglong2*)(Vs + c * DDIM + d0);
            u64 kp0 = pk1(k4.x), kp1 = pk1(k4.y), kp2 = pk1(k4.z), kp3 = pk1(k4.w);
            fma2(acc[0][0], kp0, v2.x); fma2(acc[0][1], kp0, v2.y);
            fma2(acc[1][0], kp1, v2.x); fma2(acc[1][1], kp1, v2.y);
            fma2(acc[2][0], kp2, v2.x); fma2(acc[2][1], kp2, v2.y);
            fma2(acc[3][0], kp3, v2.x); fma2(acc[3][1], kp3, v2.y);
            if (warp == 0) { ks0 += k4.x; ks1 += k4.y; ks2 += k4.z; ks3 += k4.w; }
        }
        #pragma unroll
        for (int i = 0; i < 4; ++i) {
            float x0, x1, x2, x3;
            upk(acc[i][0], x0, x1); upk(acc[i][1], x2, x3);
            float4 o = {x0, x1, x2, x3};
            *(float4*)(Sout + (m0 + i) * DDIM + d0) = o;
        }
        if (warp == 0) {
            float* kso = g_ks + (bh * NCH + chunk) * MDIM + m0;
            kso[0] = ks0; kso[1] = ks1; kso[2] = ks2; kso[3] = ks3;
        }
    }
    float* kout = g_kp + (size_t)(bh * LDIM + l0) * MDIM;
    for (int idx = tid; idx < CHK * MDIM; idx += 512) kout[idx] = kps[idx];
}

// ---------------------------------------------------------------------------
// Pass 2: in-place exclusive prefix over chunks per (b,h). grid (NBH, 32)
// ---------------------------------------------------------------------------
__global__ __launch_bounds__(256, 4) void pass2_kernel()
{
    const int bh  = blockIdx.x;
    const int e   = blockIdx.y * 256 + threadIdx.x;   // 0..8191
    float run = 0.f;
    #pragma unroll 4
    for (int c = 0; c < NCH; ++c) {
        size_t off = ((size_t)(bh * NCH + c)) * MDIM * DDIM + e;
        float cur = g_S[off];
        g_S[off] = run;
        run += cur;
    }
    if (blockIdx.y == 0 && threadIdx.x < MDIM) {
        float r2 = 0.f;
        #pragma unroll 4
        for (int c = 0; c < NCH; ++c) {
            int off = (bh * NCH + c) * MDIM + threadIdx.x;
            float cur = g_ks[off];
            g_ks[off] = r2;
            r2 += cur;
        }
    }
}

// ---------------------------------------------------------------------------
// Pass 3: qp features; out = (qp S_pref + tril(qp kp^T) V) / (qp ksum_pref + ...)
// grid (NCH, NBH), 512 threads (16 warps, 8 rows per warp, row-pair packing)
// ---------------------------------------------------------------------------
__global__ __launch_bounds__(512, 1) void pass3_kernel(
    const float* __restrict__ Q, const float* __restrict__ V,
    const float* __restrict__ P, float* __restrict__ Out)
{
    extern __shared__ float sm[];
    float* PsT   = sm;
    float* QsT   = sm + 64 * TSTRIDE;
    float* kpT   = sm;                       // stride KPTSTRIDE, reuses r0
    float* qp    = sm + 16896;
    float* Ss    = qp + 16384;
    float* ksums = Ss + MDIM * DDIM;
    float* As    = qp + 16384;               // alias of Ss region
    float* Vs    = qp + 16384 + 16384;

    const int chunk = blockIdx.x;
    const int bh    = blockIdx.y;
    const int b     = bh >> 3;
    const int h     = bh & 7;
    const int l0    = chunk * CHK;
    const int tid   = threadIdx.x;
    const int lane  = tid & 31;
    const int warp  = tid >> 5;

    const float* Sg = g_S + ((size_t)(bh * NCH + chunk)) * MDIM * DDIM;
    for (int idx = tid; idx < MDIM * DDIM; idx += 512) {
        int m = idx >> 6, d = idx & 63;
        PsT[d * TSTRIDE + m] = P[idx];
        Ss[idx] = Sg[idx];
    }
    for (int idx = tid; idx < CHK * DDIM; idx += 512) {
        int c = idx >> 6, d = idx & 63;
        size_t g = ((size_t)((b * LDIM + l0 + c) * HDIM + h)) * DDIM + d;
        QsT[d * TSTRIDE + c] = Q[g];
        Vs[c * DDIM + d]     = V[g];
    }
    if (tid < MDIM) ksums[tid] = g_ks[(bh * NCH + chunk) * MDIM + tid];
    __syncthreads();

    // qp[c][m] = relu(ratio * Q P^T) + eps
    #pragma unroll
    for (int k = 0; k < 2; ++k) {
        const int m0 = lane << 2;
        const int c0 = (warp + k * 16) << 2;
        u64 acc[4][2] = {};
        #pragma unroll 8
        for (int d = 0; d < 64; ++d) {
            float4 c4 = *(const float4*)(QsT + d * TSTRIDE + c0);
            ulonglong2 p2 = *(const ulonglong2*)(PsT + d * TSTRIDE + m0);
            u64 cp0 = pk1(c4.x), cp1 = pk1(c4.y), cp2 = pk1(c4.z), cp3 = pk1(c4.w);
            fma2(acc[0][0], cp0, p2.x); fma2(acc[0][1], cp0, p2.y);
            fma2(acc[1][0], cp1, p2.x); fma2(acc[1][1], cp1, p2.y);
            fma2(acc[2][0], cp2, p2.x); fma2(acc[2][1], cp2, p2.y);
            fma2(acc[3][0], cp3, p2.x); fma2(acc[3][1], cp3, p2.y);
        }
        #pragma unroll
        for (int i = 0; i < 4; ++i) {
            float x0, x1, x2, x3;
            upk(acc[i][0], x0, x1); upk(acc[i][1], x2, x3);
            float4 o;
            o.x = fmaxf(x0 * RATIO, 0.f) + STAB;
            o.y = fmaxf(x1 * RATIO, 0.f) + STAB;
            o.z = fmaxf(x2 * RATIO, 0.f) + STAB;
            o.w = fmaxf(x3 * RATIO, 0.f) + STAB;
            *(float4*)(qp + (c0 + i) * MDIM + m0) = o;
        }
    }
    __syncthreads();   // qp visible; r0 (PsT/QsT) free

    // Load kpT[m][c] (transposed) into r0. Conflict-free stores (stride 129).
    const float* kg = g_kp + (size_t)(bh * LDIM + l0) * MDIM;
    for (int idx = tid; idx < CHK * MDIM; idx += 512) {
        int m = idx & 127, c = idx >> 7;
        kpT[m * KPTSTRIDE + c] = kg[c * MDIM + m];
    }

    // Phase B: acc += qp @ S_pref ; den += qp . ksum_pref   (rows packed in pairs)
    const int t0 = warp * 8;
    u64 accL2[4] = {}, accH2[4] = {}, den2[4] = {};
    #pragma unroll 2
    for (int m = 0; m < MDIM; m += 4) {
        float4 qv4[8];
        #pragma unroll
        for (int i = 0; i < 8; ++i)
            qv4[i] = *(const float4*)(qp + (t0 + i) * MDIM + m);
        #pragma unroll
        for (int mm = 0; mm < 4; ++mm) {
            u64 slp = pk1(Ss[(m + mm) * DDIM + lane]);
            u64 shp = pk1(Ss[(m + mm) * DDIM + lane + 32]);
            u64 ksp = pk1(ksums[m + mm]);
            #pragma unroll
            for (int ip = 0; ip < 4; ++ip) {
                u64 qq = pk2(((const float*)&qv4[2 * ip])[mm],
                             ((const float*)&qv4[2 * ip + 1])[mm]);
                fma2(accL2[ip], qq, slp);
                fma2(accH2[ip], qq, shp);
                fma2(den2[ip],  qq, ksp);
            }
        }
    }
    __syncthreads();   // kpT ready; Ss fully consumed (As may overwrite r2)

    // Phase C: A = qp kp^T over active s-blocks (warp w: rows w*8..w*8+7)
    const int smax = t0 + 7;
    u64 a2[4][4];
    #pragma unroll
    for (int ip = 0; ip < 4; ++ip)
        #pragma unroll
        for (int j = 0; j < 4; ++j) a2[ip][j] = 0ull;

    #pragma unroll 2
    for (int m = 0; m < MDIM; m += 4) {
        float4 qv4[8];
        #pragma unroll
        for (int i = 0; i < 8; ++i)
            qv4[i] = *(const float4*)(qp + (t0 + i) * MDIM + m);
        #pragma unroll
        for (int mm = 0; mm < 4; ++mm) {
            u64 qq[4];
            #pragma unroll
            for (int ip = 0; ip < 4; ++ip)
                qq[ip] = pk2(((const float*)&qv4[2 * ip])[mm],
                             ((const float*)&qv4[2 * ip + 1])[mm]);
            #pragma unroll
            for (int j = 0; j < 4; ++j) {
                if (j * 32 <= smax) {   // warp-uniform 32-granular block skip
                    u64 kvp = pk1(kpT[(m + mm) * KPTSTRIDE + j * 32 + lane]);
                    #pragma unroll
                    for (int ip = 0; ip < 4; ++ip)
                        fma2(a2[ip][j], qq[ip], kvp);
                }
            }
        }
    }
    // Causal mask + stage into As (warp-private rows)
    #pragma unroll
    for (int ip = 0; ip < 4; ++ip) {
        int r0 = t0 + 2 * ip, r1 = r0 + 1;
        #pragma unroll
        for (int j = 0; j < 4; ++j) {
            int s = j * 32 + lane;
            if (j * 32 <= smax) {
                float x0, x1; upk(a2[ip][j], x0, x1);
                As[r0 * MDIM + s] = (s <= r0) ? x0 : 0.f;
                As[r1 * MDIM + s] = (s <= r1) ? x1 : 0.f;
            }
        }
    }
    __syncwarp();

    // Phase C2: acc += tril(A) @ V ; den += rowsum(tril(A))
    const u64 ONEp = pk1(1.0f);
    for (int s = 0; s <= smax; s += 4) {
        float4 a4[8];
        #pragma unroll
        for (int i = 0; i < 8; ++i)
            a4[i] = *(const float4*)(As + (t0 + i) * MDIM + s);
        #pragma unroll
        for (int ss = 0; ss < 4; ++ss) {
            u64 vlp = pk1(Vs[(s + ss) * DDIM + lane]);
            u64 vhp = pk1(Vs[(s + ss) * DDIM + lane + 32]);
            #pragma unroll
            for (int ip = 0; ip < 4; ++ip) {
                u64 avp = pk2(((const float*)&a4[2 * ip])[ss],
                              ((const float*)&a4[2 * ip + 1])[ss]);
                fma2(accL2[ip], avp, vlp);
                fma2(accH2[ip], avp, vhp);
                fma2(den2[ip],  avp, ONEp);
            }
        }
    }

    // Epilogue
    #pragma unroll
    for (int ip = 0; ip < 4; ++ip) {
        float lA, lB, hA, hB, dA, dB;
        upk(accL2[ip], lA, lB); upk(accH2[ip], hA, hB); upk(den2[ip], dA, dB);
        int r0 = t0 + 2 * ip;
        size_t g0 = ((size_t)((b * LDIM + l0 + r0) * HDIM + h)) * DDIM;
        size_t g1 = g0 + (size_t)HDIM * DDIM;
        float i0 = 1.0f / dA, i1 = 1.0f / dB;
        Out[g0 + lane]      = lA * i0;
        Out[g0 + lane + 32] = hA * i0;
        Out[g1 + lane]      = lB * i1;
        Out[g1 + lane + 32] = hB * i1;
    }
}

// ---------------------------------------------------------------------------
extern "C" void kernel_launch(void* const* d_in, const int* in_sizes, int n_in,
                              void* d_out, int out_size)
{
    const float* Q = (const float*)d_in[0];
    const float* K = (const float*)d_in[1];
    const float* V = (const float*)d_in[2];
    const float* P = (const float*)d_in[3];
    float* O = (float*)d_out;

    const int smem1 = (64 * TSTRIDE * 2 + CHK * MDIM + CHK * DDIM) * sizeof(float);  // 165888
    const int smem3 = (16896 + 16384 + 16384 + 8192) * sizeof(float);                // 231424

    cudaFuncSetAttribute(pass1_kernel, cudaFuncAttributeMaxDynamicSharedMemorySize, smem1);
    cudaFuncSetAttribute(pass3_kernel, cudaFuncAttributeMaxDynamicSharedMemorySize, smem3);

    pass1_kernel<<<dim3(NCH, NBH), 512, smem1>>>(K, V, P);
    pass2_kernel<<<dim3(NBH, NCH), 256>>>();
    pass3_kernel<<<dim3(NCH, NBH), 512, smem3>>>(Q, V, P, O);
}